// round 9
// baseline (speedup 1.0000x reference)
#include <cuda_runtime.h>
#include <math.h>
#include <stdint.h>

#define D_MODEL 1024
#define D_FF    4096
#define NE      8
#define NT      8192
#define ROWS_MAX 17408
#define NTILES  136             // ROWS_MAX/128 m-tiles

// ---------------- static scratch (no runtime allocation allowed) ----------------
__device__ int   g_topk_idx[NT * 2];
__device__ float g_topk_prob[NT * 2];
__device__ int   g_pos[NT * 2];
__device__ int   g_counts[NE];
__device__ float g_probs_sum[NE];
__device__ int   g_poff[NE + 1];
__device__ int   g_cursor[NE];
// fragment-ordered A buffers: per 128-row block, layout [kt][k&3][row&127][k>>2 &3]
__device__ float g_xa[(size_t)ROWS_MAX * D_MODEL];
__device__ float g_h[(size_t)ROWS_MAX * D_FF];
__device__ float g_y[(size_t)ROWS_MAX * D_MODEL];         // GEMM2 out, row-major fp32

// ---------------- PTX helpers (arch-portable only) ----------------
__device__ __forceinline__ uint32_t smem_to_u32(const void* p) {
    uint32_t a;
    asm("{ .reg .u64 t; cvta.to.shared.u64 t, %1; cvt.u32.u64 %0, t; }" : "=r"(a) : "l"(p));
    return a;
}
__device__ __forceinline__ void cp16(uint32_t s, const void* g) {
    asm volatile("cp.async.cg.shared.global [%0], [%1], 16;\n" :: "r"(s), "l"(g) : "memory");
}
#define CP_COMMIT() asm volatile("cp.async.commit_group;\n" ::: "memory")
#define CP_WAIT(n)  asm volatile("cp.async.wait_group %0;\n" :: "n"(n) : "memory")

__device__ __forceinline__ void mma_tf32(float* c, const unsigned* a, const unsigned* b) {
    asm volatile(
        "mma.sync.aligned.m16n8k8.row.col.f32.tf32.tf32.f32 "
        "{%0,%1,%2,%3}, {%4,%5,%6,%7}, {%8,%9}, {%0,%1,%2,%3};\n"
        : "+f"(c[0]), "+f"(c[1]), "+f"(c[2]), "+f"(c[3])
        : "r"(a[0]), "r"(a[1]), "r"(a[2]), "r"(a[3]), "r"(b[0]), "r"(b[1]));
}
__device__ __forceinline__ float rna_tf32(float v) {
    float r;
    asm("cvt.rna.tf32.f32 %0, %1;\n" : "=f"(r) : "f"(v));
    return r;
}
__device__ __forceinline__ float4 rna_tf32_4(float4 v) {
    v.x = rna_tf32(v.x); v.y = rna_tf32(v.y);
    v.z = rna_tf32(v.z); v.w = rna_tf32(v.w);
    return v;
}

// ---------------- init ----------------
__global__ void k_init() {
    int i = threadIdx.x;
    if (i < NE) { g_counts[i] = 0; g_probs_sum[i] = 0.f; g_cursor[i] = 0; }
}

// ---------------- router: 1 warp per token ----------------
__global__ void __launch_bounds__(256) k_router(const float* __restrict__ x,
                                                const float* __restrict__ gw,
                                                const float* __restrict__ gb) {
    __shared__ float gws[NE * D_MODEL];
    __shared__ float psum[NE];
    __shared__ int   scnt[NE];
    int tid = threadIdx.x;
    for (int i = tid; i < NE * D_MODEL; i += 256) {
        int d = i >> 3, e = i & 7;
        gws[e * D_MODEL + d] = gw[i];
    }
    if (tid < NE) { psum[tid] = 0.f; scnt[tid] = 0; }
    __syncthreads();

    int lane = tid & 31, warp = tid >> 5;
    int t = blockIdx.x * 8 + warp;
    const float* xr = x + (size_t)t * D_MODEL;

    float acc[NE];
#pragma unroll
    for (int e = 0; e < NE; e++) acc[e] = 0.f;
    for (int i = 0; i < D_MODEL / 32; i++) {
        int d = i * 32 + lane;
        float xv = xr[d];
#pragma unroll
        for (int e = 0; e < NE; e++) acc[e] += xv * gws[e * D_MODEL + d];
    }
#pragma unroll
    for (int e = 0; e < NE; e++)
        for (int off = 16; off > 0; off >>= 1)
            acc[e] += __shfl_xor_sync(0xffffffffu, acc[e], off);

    if (lane == 0) {
        float l[NE], p[NE];
        float m = -1e30f;
#pragma unroll
        for (int e = 0; e < NE; e++) { l[e] = acc[e] + gb[e]; m = fmaxf(m, l[e]); }
        float s = 0.f;
#pragma unroll
        for (int e = 0; e < NE; e++) { p[e] = expf(l[e] - m); s += p[e]; }
        float inv = 1.f / s;
#pragma unroll
        for (int e = 0; e < NE; e++) { p[e] *= inv; atomicAdd(&psum[e], p[e]); }
        int e1 = 0;
#pragma unroll
        for (int e = 1; e < NE; e++) if (p[e] > p[e1]) e1 = e;
        int e2 = -1;
#pragma unroll
        for (int e = 0; e < NE; e++) {
            if (e == e1) continue;
            if (e2 < 0 || p[e] > p[e2]) e2 = e;
        }
        float pr = 1.f / (p[e1] + p[e2]);
        g_topk_idx[2 * t] = e1;     g_topk_idx[2 * t + 1] = e2;
        g_topk_prob[2 * t] = p[e1] * pr; g_topk_prob[2 * t + 1] = p[e2] * pr;
        atomicAdd(&scnt[e1], 1);
        atomicAdd(&scnt[e2], 1);
    }
    __syncthreads();
    if (tid < NE) {
        atomicAdd(&g_probs_sum[tid], psum[tid]);
        atomicAdd(&g_counts[tid], scnt[tid]);
    }
}

// ---------------- stats + padded segment offsets ----------------
__global__ void k_stats(float* __restrict__ out) {
    if (threadIdx.x == 0) {
        int off = 0;
        for (int e = 0; e < NE; e++) {
            g_poff[e] = off;
            off += ((g_counts[e] + 127) >> 7) << 7;
        }
        g_poff[NE] = off;
        float* tail = out + (size_t)NT * D_MODEL;
        for (int e = 0; e < NE; e++) tail[e] = (float)g_counts[e] / (float)(NT * 2);
        float avg[NE], mean = 0.f;
        for (int e = 0; e < NE; e++) { avg[e] = g_probs_sum[e] / (float)NT; mean += avg[e]; }
        mean /= (float)NE;
        float var = 0.f;
        for (int e = 0; e < NE; e++) { float d = avg[e] - mean; var += d * d; }
        tail[NE] = var / (float)(NE - 1);   // ddof=1
    }
}

// ---------------- scatter slots ----------------
__global__ void k_scatter() {
    int s = blockIdx.x * blockDim.x + threadIdx.x;
    int e = g_topk_idx[s];
    int p = g_poff[e] + atomicAdd(&g_cursor[e], 1);
    g_pos[s] = p;
}

// ---------------- pack: gather x rows, tf32-round, fragment-ordered layout ------
// element (row p, k) -> block p>>7, offset (k>>4)*2048 + (k&3)*512 + (p&127)*4 + ((k>>2)&3)
__global__ void __launch_bounds__(256) k_pack(const float* __restrict__ x) {
    int s = blockIdx.x;
    int tok = s >> 1;
    int p = g_pos[s];
    int i = threadIdx.x;                 // handles k = 4i .. 4i+3
    float4 v = rna_tf32_4(*(const float4*)&x[(size_t)tok * D_MODEL + i * 4]);
    size_t base = (size_t)(p >> 7) * (128 * D_MODEL)
                + (size_t)(i >> 2) * 2048 + (p & 127) * 4 + (i & 3);
    g_xa[base]        = v.x;
    g_xa[base + 512]  = v.y;
    g_xa[base + 1024] = v.z;
    g_xa[base + 1536] = v.w;
}

// ---------------- tf32 GEMM: 128x128 block, 16-k stages, 3-stage cp.async ------
// A stage: 4 r-planes x 136 float4 (8704B, conflict-free LDS.128)
// B stage: 16 k-rows x 136 floats (8704B, raw weights; rounded in-register)
#define A_ST 2176   // floats per A stage
#define B_ST 2176   // floats per B stage
#define SMEM_GEMM ((3 * (A_ST + B_ST)) * 4)   // 52224 bytes

__device__ __forceinline__ void fill_stage(uint32_t aS, uint32_t bS,
                                           const float* __restrict__ A0,
                                           const float* __restrict__ B0,
                                           int kt, int ndim, int tid) {
#pragma unroll
    for (int i = 0; i < 2; i++) {               // A: 512 cp16 ([r][row] 16B chunks)
        int id = tid + i * 256;
        int r = id >> 7, row = id & 127;
        cp16(aS + (uint32_t)(r * 136 + row) * 16,
             A0 + (size_t)kt * 2048 + r * 512 + row * 4);
    }
#pragma unroll
    for (int i = 0; i < 2; i++) {               // B: 512 cp16 (16 k-rows x 32 chunks)
        int id = tid + i * 256;
        int k = id >> 5, ch = id & 31;
        cp16(bS + (uint32_t)(k * 136 + ch * 4) * 4,
             B0 + (size_t)(kt * 16 + k) * ndim + ch * 4);
    }
}

template <int KDIM, int NDIM, bool FIRST>
__global__ void __launch_bounds__(256, 2) k_gemm(const float* __restrict__ Bg,
                                                 const float* __restrict__ bias) {
    extern __shared__ float sm[];
    const int row0 = blockIdx.x * 128;
    if (row0 >= g_poff[NE]) return;
    int e = 0;
#pragma unroll
    for (int i = 1; i < NE; i++) if (row0 >= g_poff[i]) e = i;
    const int n0 = blockIdx.y * 128;
    const int tid = threadIdx.x, lane = tid & 31, warp = tid >> 5;
    const int wm = warp & 1, wn = warp >> 1;
    const int gid = lane >> 2, ktid = lane & 3;
    const uint32_t sb = smem_to_u32(sm);
    const uint32_t aU = sb, bU = sb + 3 * A_ST * 4;

    // device-symbol A base, fragment-ordered per 128-row block
    const float* A0 = (FIRST ? g_xa : g_h) + (size_t)blockIdx.x * 128 * KDIM;
    const float* B0 = Bg + (size_t)e * KDIM * NDIM + n0;
    const int NKT = KDIM / 16;

    fill_stage(aU, bU, A0, B0, 0, NDIM, tid);
    CP_COMMIT();
    fill_stage(aU + A_ST * 4, bU + B_ST * 4, A0, B0, 1, NDIM, tid);
    CP_COMMIT();

    float acc[4][4][4];
#pragma unroll
    for (int a = 0; a < 4; a++)
#pragma unroll
        for (int b = 0; b < 4; b++)
#pragma unroll
            for (int c = 0; c < 4; c++) acc[a][b][c] = 0.f;

#pragma unroll 1
    for (int kt = 0; kt < NKT; kt++) {
        CP_WAIT(1);
        __syncthreads();
        const int cn = kt + 2;
        if (cn < NKT) {
            const int s2 = cn % 3;
            fill_stage(aU + s2 * A_ST * 4, bU + s2 * B_ST * 4, A0, B0, cn, NDIM, tid);
        }
        CP_COMMIT();
        const float4* Af = (const float4*)(sm + (kt % 3) * A_ST);
        const float*  Bsb = sm + 3 * A_ST + (kt % 3) * B_ST;

        // B fragments: 16 scalar LDS (conflict-free) + in-register tf32 rounding
        unsigned bb[4][4];
#pragma unroll
        for (int nt = 0; nt < 4; nt++) {
            int col = wn * 32 + nt * 8 + gid;
#pragma unroll
            for (int j = 0; j < 4; j++)
                bb[nt][j] = __float_as_uint(rna_tf32(Bsb[(ktid + 4 * j) * 136 + col]));
        }
        // A fragments: 2 x LDS.128 per mt (conflict-free), covers both kk halves
#pragma unroll
        for (int mt = 0; mt < 4; mt++) {
            int row = wm * 64 + mt * 16 + gid;
            float4 lo = Af[ktid * 136 + row];
            float4 hi = Af[ktid * 136 + row + 8];
            unsigned a0[4] = { __float_as_uint(lo.x), __float_as_uint(hi.x),
                               __float_as_uint(lo.y), __float_as_uint(hi.y) };
            unsigned a1[4] = { __float_as_uint(lo.z), __float_as_uint(hi.z),
                               __float_as_uint(lo.w), __float_as_uint(hi.w) };
#pragma unroll
            for (int nt = 0; nt < 4; nt++) {
                mma_tf32(acc[mt][nt], a0, bb[nt]);        // k = kt*16 + 0..7
                mma_tf32(acc[mt][nt], a1, &bb[nt][2]);    // k = kt*16 + 8..15
            }
        }
    }

    // epilogue
#pragma unroll
    for (int mt = 0; mt < 4; mt++) {
        int rl0 = wm * 64 + mt * 16 + gid;      // tile-local rows
        int rl1 = rl0 + 8;
#pragma unroll
        for (int nt = 0; nt < 4; nt++) {
            int c = n0 + wn * 32 + nt * 8 + ktid * 2;
            float* a = acc[mt][nt];
            if (FIRST) {
                // g_h in fragment-ordered layout (it is GEMM2's A)
                float bb0 = bias[e * NDIM + c];
                float bb1 = bias[e * NDIM + c + 1];
                float v00 = rna_tf32(fmaxf(a[0] + bb0, 0.f));
                float v01 = rna_tf32(fmaxf(a[1] + bb1, 0.f));
                float v10 = rna_tf32(fmaxf(a[2] + bb0, 0.f));
                float v11 = rna_tf32(fmaxf(a[3] + bb1, 0.f));
                size_t base = (size_t)blockIdx.x * 128 * D_FF
                            + (size_t)(c >> 4) * 2048 + ((c >> 2) & 3);
                size_t o0 = base + (c & 3) * 512;        // column c
                size_t o1 = base + ((c + 1) & 3) * 512;  // column c+1 (same q: c%4<3)
                g_h[o0 + rl0 * 4] = v00;
                g_h[o1 + rl0 * 4] = v01;
                g_h[o0 + rl1 * 4] = v10;
                g_h[o1 + rl1 * 4] = v11;
            } else {
                int rr0 = row0 + rl0, rr1 = row0 + rl1;
                *(float2*)&g_y[(size_t)rr0 * D_MODEL + c] = make_float2(a[0], a[1]);
                *(float2*)&g_y[(size_t)rr1 * D_MODEL + c] = make_float2(a[2], a[3]);
            }
        }
    }
}

// ---------------- combine ----------------
__global__ void __launch_bounds__(256) k_combine(const float* __restrict__ b2,
                                                 float* __restrict__ out) {
    int t = blockIdx.x, i = threadIdx.x;
    int e0 = g_topk_idx[2 * t], e1 = g_topk_idx[2 * t + 1];
    float p0 = g_topk_prob[2 * t], p1 = g_topk_prob[2 * t + 1];
    int q0 = g_pos[2 * t], q1 = g_pos[2 * t + 1];
    float4 y0 = *(const float4*)&g_y[(size_t)q0 * D_MODEL + i * 4];
    float4 y1 = *(const float4*)&g_y[(size_t)q1 * D_MODEL + i * 4];
    float4 c0 = *(const float4*)&b2[(size_t)e0 * D_MODEL + i * 4];
    float4 c1 = *(const float4*)&b2[(size_t)e1 * D_MODEL + i * 4];
    float4 o;
    o.x = p0 * (y0.x + c0.x) + p1 * (y1.x + c1.x);
    o.y = p0 * (y0.y + c0.y) + p1 * (y1.y + c1.y);
    o.z = p0 * (y0.z + c0.z) + p1 * (y1.z + c1.z);
    o.w = p0 * (y0.w + c0.w) + p1 * (y1.w + c1.w);
    *(float4*)&out[(size_t)t * D_MODEL + i * 4] = o;
}

// ---------------- launch ----------------
extern "C" void kernel_launch(void* const* d_in, const int* in_sizes, int n_in,
                              void* d_out, int out_size) {
    (void)in_sizes; (void)n_in; (void)out_size;
    const float* x  = (const float*)d_in[0];
    const float* gw = (const float*)d_in[1];
    const float* gb = (const float*)d_in[2];
    const float* w1 = (const float*)d_in[3];
    const float* b1 = (const float*)d_in[4];
    const float* w2 = (const float*)d_in[5];
    const float* b2 = (const float*)d_in[6];
    float* out = (float*)d_out;

    static int attr_done = 0;
    if (!attr_done) {
        cudaFuncSetAttribute(k_gemm<D_MODEL, D_FF, true>,
                             cudaFuncAttributeMaxDynamicSharedMemorySize, SMEM_GEMM);
        cudaFuncSetAttribute(k_gemm<D_FF, D_MODEL, false>,
                             cudaFuncAttributeMaxDynamicSharedMemorySize, SMEM_GEMM);
        attr_done = 1;
    }

    k_init<<<1, 32>>>();
    k_router<<<NT / 8, 256>>>(x, gw, gb);
    k_stats<<<1, 32>>>(out);
    k_scatter<<<(NT * 2) / 256, 256>>>();
    k_pack<<<NT * 2, 256>>>(x);
    k_gemm<D_MODEL, D_FF, true ><<<dim3(NTILES, D_FF / 128), 256, SMEM_GEMM>>>(w1, b1);
    k_gemm<D_FF, D_MODEL, false><<<dim3(NTILES, D_MODEL / 128), 256, SMEM_GEMM>>>(w2, (const float*)0);
    k_combine<<<NT, 256>>>(b2, out);
}

// round 10
// speedup vs baseline: 1.4688x; 1.4688x over previous
#include <cuda_runtime.h>
#include <math.h>
#include <stdint.h>

#define D_MODEL 1024
#define D_FF    4096
#define NE      8
#define NT      8192
#define ROWS_MAX 17408
#define NTILES  136             // ROWS_MAX/128 m-tiles

// ---------------- static scratch (no runtime allocation allowed) ----------------
__device__ int   g_topk_idx[NT * 2];
__device__ float g_topk_prob[NT * 2];
__device__ int   g_pos[NT * 2];
__device__ int   g_counts[NE];
__device__ float g_probs_sum[NE];
__device__ int   g_poff[NE + 1];
__device__ int   g_cursor[NE];
__device__ float g_xa[(size_t)ROWS_MAX * D_MODEL];        // permuted + tf32-rounded x
__device__ float g_h[(size_t)ROWS_MAX * D_FF];            // GEMM1 out, tf32-rounded fp32
__device__ float g_y[(size_t)ROWS_MAX * D_MODEL];         // GEMM2 out fp32

// ---------------- PTX helpers (arch-portable only) ----------------
__device__ __forceinline__ uint32_t smem_to_u32(const void* p) {
    uint32_t a;
    asm("{ .reg .u64 t; cvta.to.shared.u64 t, %1; cvt.u32.u64 %0, t; }" : "=r"(a) : "l"(p));
    return a;
}
__device__ __forceinline__ void cp16(uint32_t s, const void* g) {
    asm volatile("cp.async.cg.shared.global [%0], [%1], 16;\n" :: "r"(s), "l"(g) : "memory");
}
#define CP_COMMIT() asm volatile("cp.async.commit_group;\n" ::: "memory")
#define CP_WAIT(n)  asm volatile("cp.async.wait_group %0;\n" :: "n"(n) : "memory")

__device__ __forceinline__ void mma_tf32(float* c, const unsigned* a, const unsigned* b) {
    asm volatile(
        "mma.sync.aligned.m16n8k8.row.col.f32.tf32.tf32.f32 "
        "{%0,%1,%2,%3}, {%4,%5,%6,%7}, {%8,%9}, {%0,%1,%2,%3};\n"
        : "+f"(c[0]), "+f"(c[1]), "+f"(c[2]), "+f"(c[3])
        : "r"(a[0]), "r"(a[1]), "r"(a[2]), "r"(a[3]), "r"(b[0]), "r"(b[1]));
}
__device__ __forceinline__ float rna_tf32(float v) {
    float r;
    asm("cvt.rna.tf32.f32 %0, %1;\n" : "=f"(r) : "f"(v));
    return r;
}
__device__ __forceinline__ unsigned rna_tf32_u(float v) {
    float r;
    asm("cvt.rna.tf32.f32 %0, %1;\n" : "=f"(r) : "f"(v));
    return __float_as_uint(r);
}
__device__ __forceinline__ float4 rna_tf32_4(float4 v) {
    v.x = rna_tf32(v.x); v.y = rna_tf32(v.y);
    v.z = rna_tf32(v.z); v.w = rna_tf32(v.w);
    return v;
}

// ---------------- init ----------------
__global__ void k_init() {
    int i = threadIdx.x;
    if (i < NE) { g_counts[i] = 0; g_probs_sum[i] = 0.f; g_cursor[i] = 0; }
}

// ---------------- router: 1 warp per token ----------------
__global__ void __launch_bounds__(256) k_router(const float* __restrict__ x,
                                                const float* __restrict__ gw,
                                                const float* __restrict__ gb) {
    __shared__ float gws[NE * D_MODEL];
    __shared__ float psum[NE];
    __shared__ int   scnt[NE];
    int tid = threadIdx.x;
    for (int i = tid; i < NE * D_MODEL; i += 256) {
        int d = i >> 3, e = i & 7;
        gws[e * D_MODEL + d] = gw[i];
    }
    if (tid < NE) { psum[tid] = 0.f; scnt[tid] = 0; }
    __syncthreads();

    int lane = tid & 31, warp = tid >> 5;
    int t = blockIdx.x * 8 + warp;
    const float* xr = x + (size_t)t * D_MODEL;

    float acc[NE];
#pragma unroll
    for (int e = 0; e < NE; e++) acc[e] = 0.f;
    for (int i = 0; i < D_MODEL / 32; i++) {
        int d = i * 32 + lane;
        float xv = xr[d];
#pragma unroll
        for (int e = 0; e < NE; e++) acc[e] += xv * gws[e * D_MODEL + d];
    }
#pragma unroll
    for (int e = 0; e < NE; e++)
        for (int off = 16; off > 0; off >>= 1)
            acc[e] += __shfl_xor_sync(0xffffffffu, acc[e], off);

    if (lane == 0) {
        float l[NE], p[NE];
        float m = -1e30f;
#pragma unroll
        for (int e = 0; e < NE; e++) { l[e] = acc[e] + gb[e]; m = fmaxf(m, l[e]); }
        float s = 0.f;
#pragma unroll
        for (int e = 0; e < NE; e++) { p[e] = expf(l[e] - m); s += p[e]; }
        float inv = 1.f / s;
#pragma unroll
        for (int e = 0; e < NE; e++) { p[e] *= inv; atomicAdd(&psum[e], p[e]); }
        int e1 = 0;
#pragma unroll
        for (int e = 1; e < NE; e++) if (p[e] > p[e1]) e1 = e;
        int e2 = -1;
#pragma unroll
        for (int e = 0; e < NE; e++) {
            if (e == e1) continue;
            if (e2 < 0 || p[e] > p[e2]) e2 = e;
        }
        float pr = 1.f / (p[e1] + p[e2]);
        g_topk_idx[2 * t] = e1;     g_topk_idx[2 * t + 1] = e2;
        g_topk_prob[2 * t] = p[e1] * pr; g_topk_prob[2 * t + 1] = p[e2] * pr;
        atomicAdd(&scnt[e1], 1);
        atomicAdd(&scnt[e2], 1);
    }
    __syncthreads();
    if (tid < NE) {
        atomicAdd(&g_probs_sum[tid], psum[tid]);
        atomicAdd(&g_counts[tid], scnt[tid]);
    }
}

// ---------------- stats + padded segment offsets ----------------
__global__ void k_stats(float* __restrict__ out) {
    if (threadIdx.x == 0) {
        int off = 0;
        for (int e = 0; e < NE; e++) {
            g_poff[e] = off;
            off += ((g_counts[e] + 127) >> 7) << 7;
        }
        g_poff[NE] = off;
        float* tail = out + (size_t)NT * D_MODEL;
        for (int e = 0; e < NE; e++) tail[e] = (float)g_counts[e] / (float)(NT * 2);
        float avg[NE], mean = 0.f;
        for (int e = 0; e < NE; e++) { avg[e] = g_probs_sum[e] / (float)NT; mean += avg[e]; }
        mean /= (float)NE;
        float var = 0.f;
        for (int e = 0; e < NE; e++) { float d = avg[e] - mean; var += d * d; }
        tail[NE] = var / (float)(NE - 1);   // ddof=1
    }
}

// ---------------- scatter slots ----------------
__global__ void k_scatter() {
    int s = blockIdx.x * blockDim.x + threadIdx.x;
    int e = g_topk_idx[s];
    int p = g_poff[e] + atomicAdd(&g_cursor[e], 1);
    g_pos[s] = p;
}

// ---------------- pack: gather x rows into permuted order, tf32-rounded --------
__global__ void __launch_bounds__(256) k_pack(const float* __restrict__ x) {
    int s = blockIdx.x;
    int tok = s >> 1;
    int p = g_pos[s];
    int i = threadIdx.x;
    float4 v = *(const float4*)&x[(size_t)tok * D_MODEL + i * 4];
    *(float4*)&g_xa[(size_t)p * D_MODEL + i * 4] = rna_tf32_4(v);
}

// ---------------- tf32 GEMM: 128x128 block, 16-k stages, 3-stage cp.async ------
// SMEM per stage: A 128x16 @stride20 = 10240B, B 16x128 @stride136 = 8704B
// B is RAW weights; fragments rounded to tf32 in-register (proven bit-identical R9)
#define A_ST 2560   // floats per A stage
#define B_ST 2176   // floats per B stage
#define SMEM_GEMM ((3 * (A_ST + B_ST)) * 4)   // 56832 bytes

__device__ __forceinline__ void fill_stage(uint32_t aS, uint32_t bS,
                                           const float* __restrict__ A0,
                                           const float* __restrict__ B0,
                                           int koff, int kdim, int ndim, int tid) {
#pragma unroll
    for (int i = 0; i < 2; i++) {               // A: 512 cp16 (128 rows x 4 chunks)
        int id = tid + i * 256;
        int row = id >> 2, q = id & 3;
        cp16(aS + (uint32_t)(row * 20 + q * 4) * 4,
             A0 + (size_t)row * kdim + koff + q * 4);
    }
#pragma unroll
    for (int i = 0; i < 2; i++) {               // B: 512 cp16 (16 k-rows x 32 chunks)
        int id = tid + i * 256;
        int k = id >> 5, ch = id & 31;
        cp16(bS + (uint32_t)(k * 136 + ch * 4) * 4,
             B0 + (size_t)(koff + k) * ndim + ch * 4);
    }
}

template <int KDIM, int NDIM, bool FIRST>
__global__ void __launch_bounds__(256, 2) k_gemm(const float* __restrict__ Bg,
                                                 const float* __restrict__ bias) {
    extern __shared__ float sm[];
    const int row0 = blockIdx.x * 128;
    if (row0 >= g_poff[NE]) return;
    int e = 0;
#pragma unroll
    for (int i = 1; i < NE; i++) if (row0 >= g_poff[i]) e = i;
    const int n0 = blockIdx.y * 128;
    const int tid = threadIdx.x, lane = tid & 31, warp = tid >> 5;
    const int wm = warp & 1, wn = warp >> 1;
    const int gid = lane >> 2, ktid = lane & 3;
    const uint32_t sb = smem_to_u32(sm);
    const uint32_t aU = sb, bU = sb + 3 * A_ST * 4;

    // resolve device symbols IN DEVICE CODE (host symbol decay = garbage ptr)
    const float* A0 = (FIRST ? g_xa : g_h) + (size_t)row0 * KDIM;
    const float* B0 = Bg + (size_t)e * KDIM * NDIM + n0;
    const int NKT = KDIM / 16;

    // prologue: 2 stages in flight
    fill_stage(aU, bU, A0, B0, 0, KDIM, NDIM, tid);
    CP_COMMIT();
    fill_stage(aU + A_ST * 4, bU + B_ST * 4, A0, B0, 16, KDIM, NDIM, tid);
    CP_COMMIT();

    float acc[4][4][4];
#pragma unroll
    for (int a = 0; a < 4; a++)
#pragma unroll
        for (int b = 0; b < 4; b++)
#pragma unroll
            for (int c = 0; c < 4; c++) acc[a][b][c] = 0.f;

#pragma unroll 1
    for (int kt = 0; kt < NKT; kt++) {
        CP_WAIT(1);
        __syncthreads();
        const int cn = kt + 2;
        if (cn < NKT) {
            const int s2 = cn % 3;
            fill_stage(aU + s2 * A_ST * 4, bU + s2 * B_ST * 4,
                       A0, B0, cn * 16, KDIM, NDIM, tid);
        }
        CP_COMMIT();
        const float* Asb = sm + (kt % 3) * A_ST;
        const float* Bsb = sm + 3 * A_ST + (kt % 3) * B_ST;
#pragma unroll
        for (int kk = 0; kk < 16; kk += 8) {
            unsigned a[4][4], b[4][2];
#pragma unroll
            for (int mt = 0; mt < 4; mt++) {
                int rb_ = wm * 64 + mt * 16;
                a[mt][0] = __float_as_uint(Asb[(rb_ + gid) * 20 + kk + ktid]);
                a[mt][1] = __float_as_uint(Asb[(rb_ + gid + 8) * 20 + kk + ktid]);
                a[mt][2] = __float_as_uint(Asb[(rb_ + gid) * 20 + kk + ktid + 4]);
                a[mt][3] = __float_as_uint(Asb[(rb_ + gid + 8) * 20 + kk + ktid + 4]);
            }
#pragma unroll
            for (int nt = 0; nt < 4; nt++) {
                int col = wn * 32 + nt * 8 + gid;
                b[nt][0] = rna_tf32_u(Bsb[(kk + ktid) * 136 + col]);
                b[nt][1] = rna_tf32_u(Bsb[(kk + ktid + 4) * 136 + col]);
            }
#pragma unroll
            for (int mt = 0; mt < 4; mt++)
#pragma unroll
                for (int nt = 0; nt < 4; nt++) mma_tf32(acc[mt][nt], a[mt], b[nt]);
        }
    }

    // epilogue
#pragma unroll
    for (int mt = 0; mt < 4; mt++) {
        int rr0 = row0 + wm * 64 + mt * 16 + gid;
        int rr1 = rr0 + 8;
#pragma unroll
        for (int nt = 0; nt < 4; nt++) {
            int c = n0 + wn * 32 + nt * 8 + ktid * 2;
            float* a = acc[mt][nt];
            if (FIRST) {
                float bb0 = bias[e * NDIM + c];
                float bb1 = bias[e * NDIM + c + 1];
                float2 v0, v1;
                v0.x = rna_tf32(fmaxf(a[0] + bb0, 0.f));
                v0.y = rna_tf32(fmaxf(a[1] + bb1, 0.f));
                v1.x = rna_tf32(fmaxf(a[2] + bb0, 0.f));
                v1.y = rna_tf32(fmaxf(a[3] + bb1, 0.f));
                *(float2*)&g_h[(size_t)rr0 * D_FF + c] = v0;
                *(float2*)&g_h[(size_t)rr1 * D_FF + c] = v1;
            } else {
                *(float2*)&g_y[(size_t)rr0 * D_MODEL + c] = make_float2(a[0], a[1]);
                *(float2*)&g_y[(size_t)rr1 * D_MODEL + c] = make_float2(a[2], a[3]);
            }
        }
    }
}

// ---------------- combine ----------------
__global__ void __launch_bounds__(256) k_combine(const float* __restrict__ b2,
                                                 float* __restrict__ out) {
    int t = blockIdx.x, i = threadIdx.x;
    int e0 = g_topk_idx[2 * t], e1 = g_topk_idx[2 * t + 1];
    float p0 = g_topk_prob[2 * t], p1 = g_topk_prob[2 * t + 1];
    int q0 = g_pos[2 * t], q1 = g_pos[2 * t + 1];
    float4 y0 = *(const float4*)&g_y[(size_t)q0 * D_MODEL + i * 4];
    float4 y1 = *(const float4*)&g_y[(size_t)q1 * D_MODEL + i * 4];
    float4 c0 = *(const float4*)&b2[(size_t)e0 * D_MODEL + i * 4];
    float4 c1 = *(const float4*)&b2[(size_t)e1 * D_MODEL + i * 4];
    float4 o;
    o.x = p0 * (y0.x + c0.x) + p1 * (y1.x + c1.x);
    o.y = p0 * (y0.y + c0.y) + p1 * (y1.y + c1.y);
    o.z = p0 * (y0.z + c0.z) + p1 * (y1.z + c1.z);
    o.w = p0 * (y0.w + c0.w) + p1 * (y1.w + c1.w);
    *(float4*)&out[(size_t)t * D_MODEL + i * 4] = o;
}

// ---------------- launch ----------------
extern "C" void kernel_launch(void* const* d_in, const int* in_sizes, int n_in,
                              void* d_out, int out_size) {
    (void)in_sizes; (void)n_in; (void)out_size;
    const float* x  = (const float*)d_in[0];
    const float* gw = (const float*)d_in[1];
    const float* gb = (const float*)d_in[2];
    const float* w1 = (const float*)d_in[3];
    const float* b1 = (const float*)d_in[4];
    const float* w2 = (const float*)d_in[5];
    const float* b2 = (const float*)d_in[6];
    float* out = (float*)d_out;

    static int attr_done = 0;
    if (!attr_done) {
        cudaFuncSetAttribute(k_gemm<D_MODEL, D_FF, true>,
                             cudaFuncAttributeMaxDynamicSharedMemorySize, SMEM_GEMM);
        cudaFuncSetAttribute(k_gemm<D_FF, D_MODEL, false>,
                             cudaFuncAttributeMaxDynamicSharedMemorySize, SMEM_GEMM);
        attr_done = 1;
    }

    k_init<<<1, 32>>>();
    k_router<<<NT / 8, 256>>>(x, gw, gb);
    k_stats<<<1, 32>>>(out);
    k_scatter<<<(NT * 2) / 256, 256>>>();
    k_pack<<<NT * 2, 256>>>(x);
    k_gemm<D_MODEL, D_FF, true ><<<dim3(NTILES, D_FF / 128), 256, SMEM_GEMM>>>(w1, b1);
    k_gemm<D_FF, D_MODEL, false><<<dim3(NTILES, D_MODEL / 128), 256, SMEM_GEMM>>>(w2, (const float*)0);
    k_combine<<<NT, 256>>>(b2, out);
}